// round 5
// baseline (speedup 1.0000x reference)
#include <cuda_runtime.h>
#include <math.h>

#define M_NODES 100000
#define N_NODES 14000
#define H_DIM   256
#define K1_N    16
#define K2_N    32
#define K_ALL   48
#define C_CLS   7
#define B_BTL   64
#define PER_CLASS (N_NODES / C_CLS)   // 2000
#define EPSF 1e-8f

// Scratch (device globals — no runtime allocation allowed)
__device__ float g_rawret[N_NODES * H_DIM];     // 14.3 MB
__device__ float g_classsum[C_CLS * H_DIM];
__device__ float g_invn[C_CLS];

struct SmemA {
    float nb[K_ALL * H_DIM];   // 49152 B, weighted neighbor tile
    float ce[H_DIM];
    float wn[H_DIM];
    float wn2[H_DIM];
    float inputs[H_DIM];
    float part[4 * B_BTL];
    float hidden[B_BTL];
    float sims[K_ALL];
    float wk[K_ALL];
    float red[8];
};

__device__ __forceinline__ float dot4(float4 a, float4 b) {
    return a.x * b.x + a.y * b.y + a.z * b.z + a.w * b.w;
}

// ---------------- Kernel A: per-node rawret ----------------
__global__ void __launch_bounds__(256) kA(
    const float* __restrict__ emb,
    const float* __restrict__ w_self, const float* __restrict__ w_n,
    const float* __restrict__ w_n2,
    const float* __restrict__ W1, const float* __restrict__ b1,
    const float* __restrict__ W2, const float* __restrict__ b2,
    const int* __restrict__ idx, const int* __restrict__ nbr,
    const int* __restrict__ nbr2)
{
    extern __shared__ char smem_raw[];
    SmemA* s = reinterpret_cast<SmemA*>(smem_raw);
    const int n = blockIdx.x;
    const int t = threadIdx.x;
    const int lane = t & 31, wid = t >> 5;
    const float4* emb4 = reinterpret_cast<const float4*>(emb);

    // ---- ce = w_self * embeds[idx[n]] ; ||ce||^2 ; stage wn/wn2 to smem ----
    const int ci = idx[n];
    if (t < 64) {
        float4 ws = reinterpret_cast<const float4*>(w_self)[t];
        float4 e  = emb4[(size_t)ci * 64 + t];
        float4 c  = make_float4(ws.x * e.x, ws.y * e.y, ws.z * e.z, ws.w * e.w);
        reinterpret_cast<float4*>(s->ce)[t] = c;
        float p = dot4(c, c);
        #pragma unroll
        for (int o = 16; o; o >>= 1) p += __shfl_xor_sync(0xffffffffu, p, o);
        if (lane == 0) s->red[wid] = p;
    } else if (t < 128) {
        reinterpret_cast<float4*>(s->wn)[t - 64] =
            reinterpret_cast<const float4*>(w_n)[t - 64];
    } else if (t < 192) {
        reinterpret_cast<float4*>(s->wn2)[t - 128] =
            reinterpret_cast<const float4*>(w_n2)[t - 128];
    }
    __syncthreads();
    const float na = fmaxf(sqrtf(s->red[0] + s->red[1]), EPSF);

    // ---- gather 48 neighbor rows: weight, store tile, dot & norm per row ----
    int js[6];
    #pragma unroll
    for (int i = 0; i < 6; i++) {
        int k = wid + 8 * i;
        js[i] = (k < K1_N) ? nbr[n * K1_N + k] : nbr2[n * K2_N + (k - K1_N)];
    }
    const float4* ce4 = reinterpret_cast<const float4*>(s->ce);
    #pragma unroll
    for (int i = 0; i < 6; i++) {
        int k = wid + 8 * i;
        const float4* cf4 = reinterpret_cast<const float4*>((k < K1_N) ? s->wn : s->wn2);
        size_t base = (size_t)js[i] * 64;
        float4 v0 = emb4[base + lane];
        float4 v1 = emb4[base + 32 + lane];
        float4 c0 = cf4[lane], c1 = cf4[32 + lane];
        v0.x *= c0.x; v0.y *= c0.y; v0.z *= c0.z; v0.w *= c0.w;
        v1.x *= c1.x; v1.y *= c1.y; v1.z *= c1.z; v1.w *= c1.w;
        float4 a0 = ce4[lane], a1 = ce4[32 + lane];
        float d  = dot4(v0, a0) + dot4(v1, a1);
        float nn = dot4(v0, v0) + dot4(v1, v1);
        reinterpret_cast<float4*>(s->nb)[k * 64 + lane]      = v0;
        reinterpret_cast<float4*>(s->nb)[k * 64 + 32 + lane] = v1;
        #pragma unroll
        for (int o = 16; o; o >>= 1) {
            d  += __shfl_xor_sync(0xffffffffu, d, o);
            nn += __shfl_xor_sync(0xffffffffu, nn, o);
        }
        if (lane == 0) {
            float nbn = fmaxf(sqrtf(nn), EPSF);
            s->sims[k] = d / (na * nbn);
        }
    }
    __syncthreads();

    // ---- softmax over 48 sims (warp 0) ----
    if (wid == 0) {
        float s0 = s->sims[lane];
        float s1 = (lane < 16) ? s->sims[32 + lane] : -INFINITY;
        float m = fmaxf(s0, s1);
        #pragma unroll
        for (int o = 16; o; o >>= 1) m = fmaxf(m, __shfl_xor_sync(0xffffffffu, m, o));
        float e0 = __expf(s0 - m);
        float e1 = (lane < 16) ? __expf(s1 - m) : 0.f;
        float ts = e0 + e1;
        #pragma unroll
        for (int o = 16; o; o >>= 1) ts += __shfl_xor_sync(0xffffffffu, ts, o);
        float inv = 1.f / ts;
        s->wk[lane] = e0 * inv;
        if (lane < 16) s->wk[32 + lane] = e1 * inv;
    }
    __syncthreads();

    // ---- weighted neighbor sum + ce ----
    float acc = s->ce[t];
    #pragma unroll
    for (int k = 0; k < K_ALL; k++) acc += s->wk[k] * s->nb[k * H_DIM + t];
    s->inputs[t] = acc;
    __syncthreads();

    // ---- adapter: hidden = elu(inputs @ W1 + b1) ----
    {
        int b = t & 63, g = t >> 6;
        float hp = 0.f;
        const float* w1p = W1 + (size_t)(g * 64) * 64 + b;
        const float* inp = s->inputs + g * 64;
        #pragma unroll 8
        for (int h = 0; h < 64; h++) hp += inp[h] * w1p[h * 64];
        s->part[g * 64 + b] = hp;
    }
    __syncthreads();
    if (t < 64) {
        float hs = s->part[t] + s->part[64 + t] + s->part[128 + t] + s->part[192 + t] + b1[t];
        s->hidden[t] = (hs > 0.f) ? hs : expm1f(hs);
    }
    __syncthreads();

    // ---- prompts = hidden @ W2 + b2 ; rawret = prompts + ce ----
    float p = b2[t];
    #pragma unroll 8
    for (int bb = 0; bb < 64; bb++) p += s->hidden[bb] * W2[(size_t)bb * H_DIM + t];
    g_rawret[(size_t)n * H_DIM + t] = p + s->ce[t];
}

// ---------------- Kernel Z: zero class sums ----------------
__global__ void kZ() {
    int i = blockIdx.x * 256 + threadIdx.x;
    if (i < C_CLS * H_DIM) g_classsum[i] = 0.f;
}

// ---------------- Kernel B: per-class reduction ----------------
__global__ void __launch_bounds__(256) kB(const int* __restrict__ labels) {
    __shared__ float part[C_CLS * H_DIM];
    const int t = threadIdx.x;
    #pragma unroll
    for (int c = 0; c < C_CLS; c++) part[c * H_DIM + t] = 0.f;
    __syncthreads();
    const int base = blockIdx.x * 125;   // 112 blocks * 125 = 14000
    for (int j = 0; j < 125; j++) {
        int node = base + j;
        int c = labels[node];
        part[c * H_DIM + t] += g_rawret[(size_t)node * H_DIM + t];
    }
    __syncthreads();
    #pragma unroll
    for (int c = 0; c < C_CLS; c++)
        atomicAdd(&g_classsum[c * H_DIM + t], part[c * H_DIM + t]);
}

// ---------------- Kernel Norm: 1/||classsum_c|| ----------------
__global__ void kNorm() {
    int w = threadIdx.x >> 5, lane = threadIdx.x & 31;
    if (w < C_CLS) {
        float sq = 0.f;
        #pragma unroll
        for (int i = 0; i < 8; i++) {
            float v = g_classsum[w * H_DIM + lane + 32 * i];
            sq += v * v;
        }
        #pragma unroll
        for (int o = 16; o; o >>= 1) sq += __shfl_xor_sync(0xffffffffu, sq, o);
        // cos is scale-invariant in ave; clamp at 2000*EPS to mirror ref clamp on ||ave||
        if (lane == 0) g_invn[w] = 1.f / fmaxf(sqrtf(sq), (float)PER_CLASS * EPSF);
    }
}

// ---------------- Kernel C: final cos + softmax over classes ----------------
__global__ void __launch_bounds__(256) kC(float* __restrict__ out) {
    __shared__ float cs[C_CLS * H_DIM];
    __shared__ float invn_s[8];
    const int t = threadIdx.x;
    #pragma unroll
    for (int c = 0; c < C_CLS; c++) cs[c * H_DIM + t] = g_classsum[c * H_DIM + t];
    if (t < C_CLS) invn_s[t] = g_invn[t];
    __syncthreads();
    const int lane = t & 31, wid = t >> 5;
    const int n = blockIdx.x * 8 + wid;
    if (n >= N_NODES) return;
    const float4* rr4 = reinterpret_cast<const float4*>(g_rawret + (size_t)n * H_DIM);
    float4 r0 = rr4[lane], r1 = rr4[32 + lane];
    float nrm = dot4(r0, r0) + dot4(r1, r1);
    float d[C_CLS];
    const float4* cs4 = reinterpret_cast<const float4*>(cs);
    #pragma unroll
    for (int c = 0; c < C_CLS; c++) {
        float4 a0 = cs4[c * 64 + lane], a1 = cs4[c * 64 + 32 + lane];
        d[c] = dot4(r0, a0) + dot4(r1, a1);
    }
    #pragma unroll
    for (int o = 16; o; o >>= 1) {
        nrm += __shfl_xor_sync(0xffffffffu, nrm, o);
        #pragma unroll
        for (int c = 0; c < C_CLS; c++) d[c] += __shfl_xor_sync(0xffffffffu, d[c], o);
    }
    float inv_r = 1.f / fmaxf(sqrtf(nrm), EPSF);
    float cosv[C_CLS];
    float mx = -INFINITY;
    #pragma unroll
    for (int c = 0; c < C_CLS; c++) {
        cosv[c] = d[c] * inv_r * invn_s[c];
        mx = fmaxf(mx, cosv[c]);
    }
    float ssum = 0.f;
    #pragma unroll
    for (int c = 0; c < C_CLS; c++) {
        cosv[c] = __expf(cosv[c] - mx);
        ssum += cosv[c];
    }
    float inv = 1.f / ssum;
    if (lane < C_CLS) out[n * C_CLS + lane] = cosv[lane] * inv;
}

extern "C" void kernel_launch(void* const* d_in, const int* in_sizes, int n_in,
                              void* d_out, int out_size) {
    const float* emb    = (const float*)d_in[0];
    const float* w_self = (const float*)d_in[1];
    const float* w_n    = (const float*)d_in[2];
    const float* w_n2   = (const float*)d_in[3];
    const float* W1     = (const float*)d_in[4];
    const float* b1     = (const float*)d_in[5];
    const float* W2     = (const float*)d_in[6];
    const float* b2     = (const float*)d_in[7];
    const int*   idx    = (const int*)d_in[8];
    const int*   nbr    = (const int*)d_in[9];
    const int*   nbr2   = (const int*)d_in[10];
    const int*   labels = (const int*)d_in[11];
    float* out = (float*)d_out;

    const int smemA = (int)sizeof(SmemA);
    cudaFuncSetAttribute(kA, cudaFuncAttributeMaxDynamicSharedMemorySize, smemA);

    kZ<<<C_CLS, 256>>>();
    kA<<<N_NODES, 256, smemA>>>(emb, w_self, w_n, w_n2, W1, b1, W2, b2,
                                idx, nbr, nbr2);
    kB<<<112, 256>>>(labels);
    kNorm<<<1, 256>>>();
    kC<<<(N_NODES + 7) / 8, 256>>>(out);
}

// round 9
// speedup vs baseline: 1.0098x; 1.0098x over previous
#include <cuda_runtime.h>
#include <math.h>

#define M_NODES 100000
#define N_NODES 14000
#define H_DIM   256
#define K1_N    16
#define K2_N    32
#define K_ALL   48
#define C_CLS   7
#define B_BTL   64
#define PER_CLASS (N_NODES / C_CLS)   // 2000
#define EPSF 1e-8f

// Scratch (device globals — no runtime allocation allowed)
__device__ float g_rawret[N_NODES * H_DIM];     // 14.3 MB
__device__ float g_inputs[N_NODES * H_DIM];     // 14.3 MB
__device__ float g_ce[N_NODES * H_DIM];         // 14.3 MB
__device__ float g_classsum[C_CLS * H_DIM];
__device__ float g_invn[C_CLS];

struct SmemA {
    float nb[K_ALL * H_DIM];   // 48 KB, weighted neighbor tile
    float ce[H_DIM];
    float wn[H_DIM];
    float wn2[H_DIM];
    float sims[K_ALL];
    float wk[K_ALL];
    float red[8];
};

__device__ __forceinline__ float dot4(float4 a, float4 b) {
    return a.x * b.x + a.y * b.y + a.z * b.z + a.w * b.w;
}

// ---- packed f32x2 helpers (sm_103a) ----
__device__ __forceinline__ unsigned long long pk2(float lo, float hi) {
    unsigned long long r;
    asm("mov.b64 %0, {%1, %2};" : "=l"(r) : "f"(lo), "f"(hi));
    return r;
}
__device__ __forceinline__ void fma2(unsigned long long& d,
                                     unsigned long long a, unsigned long long b) {
    asm("fma.rn.f32x2 %0, %1, %2, %0;" : "+l"(d) : "l"(a), "l"(b));
}
__device__ __forceinline__ void unpk2(unsigned long long v, float& lo, float& hi) {
    asm("mov.b64 {%0, %1}, %2;" : "=f"(lo), "=f"(hi) : "l"(v));
}

// ---------------- Kernel A: per-node inputs + ce (no adapter) ----------------
__global__ void __launch_bounds__(256) kA(
    const float* __restrict__ emb,
    const float* __restrict__ w_self, const float* __restrict__ w_n,
    const float* __restrict__ w_n2,
    const int* __restrict__ idx, const int* __restrict__ nbr,
    const int* __restrict__ nbr2)
{
    extern __shared__ char smem_raw[];
    SmemA* s = reinterpret_cast<SmemA*>(smem_raw);
    const int n = blockIdx.x;
    const int t = threadIdx.x;
    const int lane = t & 31, wid = t >> 5;
    const float4* emb4 = reinterpret_cast<const float4*>(emb);

    // ---- ce = w_self * embeds[idx[n]] ; ||ce||^2 ; stage wn/wn2 to smem ----
    const int ci = idx[n];
    if (t < 64) {
        float4 ws = reinterpret_cast<const float4*>(w_self)[t];
        float4 e  = emb4[(size_t)ci * 64 + t];
        float4 c  = make_float4(ws.x * e.x, ws.y * e.y, ws.z * e.z, ws.w * e.w);
        reinterpret_cast<float4*>(s->ce)[t] = c;
        float p = dot4(c, c);
        #pragma unroll
        for (int o = 16; o; o >>= 1) p += __shfl_xor_sync(0xffffffffu, p, o);
        if (lane == 0) s->red[wid] = p;
    } else if (t < 128) {
        reinterpret_cast<float4*>(s->wn)[t - 64] =
            reinterpret_cast<const float4*>(w_n)[t - 64];
    } else if (t < 192) {
        reinterpret_cast<float4*>(s->wn2)[t - 128] =
            reinterpret_cast<const float4*>(w_n2)[t - 128];
    }
    __syncthreads();
    const float na = fmaxf(sqrtf(s->red[0] + s->red[1]), EPSF);

    // ---- gather 48 neighbor rows: weight, store tile, dot & norm per row ----
    int js[6];
    #pragma unroll
    for (int i = 0; i < 6; i++) {
        int k = wid + 8 * i;
        js[i] = (k < K1_N) ? nbr[n * K1_N + k] : nbr2[n * K2_N + (k - K1_N)];
    }
    const float4* ce4 = reinterpret_cast<const float4*>(s->ce);
    #pragma unroll
    for (int i = 0; i < 6; i++) {
        int k = wid + 8 * i;
        const float4* cf4 = reinterpret_cast<const float4*>((k < K1_N) ? s->wn : s->wn2);
        size_t base = (size_t)js[i] * 64;
        float4 v0 = emb4[base + lane];
        float4 v1 = emb4[base + 32 + lane];
        float4 c0 = cf4[lane], c1 = cf4[32 + lane];
        v0.x *= c0.x; v0.y *= c0.y; v0.z *= c0.z; v0.w *= c0.w;
        v1.x *= c1.x; v1.y *= c1.y; v1.z *= c1.z; v1.w *= c1.w;
        float4 a0 = ce4[lane], a1 = ce4[32 + lane];
        float d  = dot4(v0, a0) + dot4(v1, a1);
        float nn = dot4(v0, v0) + dot4(v1, v1);
        reinterpret_cast<float4*>(s->nb)[k * 64 + lane]      = v0;
        reinterpret_cast<float4*>(s->nb)[k * 64 + 32 + lane] = v1;
        #pragma unroll
        for (int o = 16; o; o >>= 1) {
            d  += __shfl_xor_sync(0xffffffffu, d, o);
            nn += __shfl_xor_sync(0xffffffffu, nn, o);
        }
        if (lane == 0) {
            float nbn = fmaxf(sqrtf(nn), EPSF);
            s->sims[k] = d / (na * nbn);
        }
    }
    __syncthreads();

    // ---- softmax over 48 sims (warp 0) ----
    if (wid == 0) {
        float s0 = s->sims[lane];
        float s1 = (lane < 16) ? s->sims[32 + lane] : -INFINITY;
        float m = fmaxf(s0, s1);
        #pragma unroll
        for (int o = 16; o; o >>= 1) m = fmaxf(m, __shfl_xor_sync(0xffffffffu, m, o));
        float e0 = __expf(s0 - m);
        float e1 = (lane < 16) ? __expf(s1 - m) : 0.f;
        float ts = e0 + e1;
        #pragma unroll
        for (int o = 16; o; o >>= 1) ts += __shfl_xor_sync(0xffffffffu, ts, o);
        float inv = 1.f / ts;
        s->wk[lane] = e0 * inv;
        if (lane < 16) s->wk[32 + lane] = e1 * inv;
    }
    __syncthreads();

    // ---- weighted neighbor sum + ce -> g_inputs ; ce -> g_ce ----
    float cev = s->ce[t];
    float acc = cev;
    #pragma unroll
    for (int k = 0; k < K_ALL; k++) acc += s->wk[k] * s->nb[k * H_DIM + t];
    g_inputs[(size_t)n * H_DIM + t] = acc;
    g_ce[(size_t)n * H_DIM + t] = cev;
}

// ---------------- Kernel Adapt: batched adapter GEMM ----------------
// rawret = elu(inputs @ W1 + b1) @ W2 + b2 + ce
// 128 nodes / block, 256 threads: tx = t%8 (8 cols of 8-stride), ty = t/8 (4 nodes)
#define AB_N 128
#define P_IN 68     // pitch for [node][64-h-chunk] tiles

struct SmemAd {
    float s_in[AB_N * P_IN];                 // inputs chunk [n][64h]   34.8 KB
    float hs[AB_N * P_IN];                   // hidden       [n][64b]   34.8 KB
    unsigned long long W1d[64 * 64];         // dup-packed W1 chunk     32 KB
    unsigned long long W2d[64 * 64];         // dup-packed W2 chunk     32 KB
};

__global__ void __launch_bounds__(256) kAdapt(
    const float* __restrict__ W1, const float* __restrict__ b1,
    const float* __restrict__ W2, const float* __restrict__ b2)
{
    extern __shared__ char smem_raw[];
    SmemAd* s = reinterpret_cast<SmemAd*>(smem_raw);
    const int t = threadIdx.x;
    const int tx = t & 7, ty = t >> 3;
    const int nb = blockIdx.x * AB_N;
    const float4* in4 = reinterpret_cast<const float4*>(g_inputs);
    const float4* W1_4 = reinterpret_cast<const float4*>(W1);
    const float4* W2_4 = reinterpret_cast<const float4*>(W2);

    // ================= GEMM1: hidden = elu(inputs @ W1 + b1) =================
    unsigned long long acc[2][8];
    #pragma unroll
    for (int p = 0; p < 2; p++)
        #pragma unroll
        for (int j = 0; j < 8; j++) acc[p][j] = 0ull;

    for (int hc = 0; hc < 4; hc++) {
        __syncthreads();
        // stage inputs chunk [128 n][64 h] (pitch 68)
        #pragma unroll
        for (int i = 0; i < 8; i++) {
            int id = t + 256 * i;               // 2048 float4
            int node = id >> 4, q = id & 15;
            float4 v = make_float4(0.f, 0.f, 0.f, 0.f);
            if (nb + node < N_NODES)
                v = in4[(size_t)(nb + node) * 64 + hc * 16 + q];
            *reinterpret_cast<float4*>(&s->s_in[node * P_IN + q * 4]) = v;
        }
        // stage W1 chunk [64 h][64 b], duplicated pairs
        #pragma unroll
        for (int i = 0; i < 4; i++) {
            int id = t + 256 * i;               // 1024 float4
            int hl = id >> 4, q = id & 15;
            float4 v = W1_4[(size_t)(hc * 64 + hl) * 16 + q];
            s->W1d[hl * 64 + q * 4 + 0] = pk2(v.x, v.x);
            s->W1d[hl * 64 + q * 4 + 1] = pk2(v.y, v.y);
            s->W1d[hl * 64 + q * 4 + 2] = pk2(v.z, v.z);
            s->W1d[hl * 64 + q * 4 + 3] = pk2(v.w, v.w);
        }
        __syncthreads();

        #pragma unroll 4
        for (int h = 0; h < 64; h++) {
            float a0 = s->s_in[(ty * 4 + 0) * P_IN + h];
            float a1 = s->s_in[(ty * 4 + 1) * P_IN + h];
            float a2 = s->s_in[(ty * 4 + 2) * P_IN + h];
            float a3 = s->s_in[(ty * 4 + 3) * P_IN + h];
            unsigned long long pa0 = pk2(a0, a1);
            unsigned long long pa1 = pk2(a2, a3);
            #pragma unroll
            for (int j = 0; j < 8; j++) {
                unsigned long long w = s->W1d[h * 64 + tx + 8 * j];
                fma2(acc[0][j], pa0, w);
                fma2(acc[1][j], pa1, w);
            }
        }
    }
    // epilogue GEMM1: + b1, elu, store hs[n][b]
    #pragma unroll
    for (int j = 0; j < 8; j++) {
        float bv = b1[tx + 8 * j];
        #pragma unroll
        for (int p = 0; p < 2; p++) {
            float lo, hi;
            unpk2(acc[p][j], lo, hi);
            lo += bv; hi += bv;
            lo = (lo > 0.f) ? lo : expm1f(lo);
            hi = (hi > 0.f) ? hi : expm1f(hi);
            s->hs[(ty * 4 + 2 * p + 0) * P_IN + tx + 8 * j] = lo;
            s->hs[(ty * 4 + 2 * p + 1) * P_IN + tx + 8 * j] = hi;
        }
    }

    // ================= GEMM2: rawret = hidden @ W2 + b2 + ce =================
    for (int oc = 0; oc < 4; oc++) {
        __syncthreads();   // prior oc's W2d reads done; hs complete (oc==0)
        #pragma unroll
        for (int i = 0; i < 4; i++) {
            int id = t + 256 * i;               // 1024 float4
            int kl = id >> 4, q = id & 15;
            float4 v = W2_4[(size_t)kl * 64 + oc * 16 + q];
            s->W2d[kl * 64 + q * 4 + 0] = pk2(v.x, v.x);
            s->W2d[kl * 64 + q * 4 + 1] = pk2(v.y, v.y);
            s->W2d[kl * 64 + q * 4 + 2] = pk2(v.z, v.z);
            s->W2d[kl * 64 + q * 4 + 3] = pk2(v.w, v.w);
        }
        __syncthreads();

        unsigned long long oacc[2][8];
        #pragma unroll
        for (int p = 0; p < 2; p++)
            #pragma unroll
            for (int j = 0; j < 8; j++) oacc[p][j] = 0ull;

        #pragma unroll 4
        for (int k = 0; k < 64; k++) {
            float a0 = s->hs[(ty * 4 + 0) * P_IN + k];
            float a1 = s->hs[(ty * 4 + 1) * P_IN + k];
            float a2 = s->hs[(ty * 4 + 2) * P_IN + k];
            float a3 = s->hs[(ty * 4 + 3) * P_IN + k];
            unsigned long long pa0 = pk2(a0, a1);
            unsigned long long pa1 = pk2(a2, a3);
            #pragma unroll
            for (int j = 0; j < 8; j++) {
                unsigned long long w = s->W2d[k * 64 + tx + 8 * j];
                fma2(oacc[0][j], pa0, w);
                fma2(oacc[1][j], pa1, w);
            }
        }
        // epilogue: + b2 + ce -> g_rawret
        #pragma unroll
        for (int j = 0; j < 8; j++) {
            int hh = oc * 64 + tx + 8 * j;
            float bv = b2[hh];
            #pragma unroll
            for (int p = 0; p < 2; p++) {
                float lo, hi;
                unpk2(oacc[p][j], lo, hi);
                int n0 = nb + ty * 4 + 2 * p;
                if (n0 < N_NODES)
                    g_rawret[(size_t)n0 * H_DIM + hh] = lo + bv + g_ce[(size_t)n0 * H_DIM + hh];
                if (n0 + 1 < N_NODES)
                    g_rawret[(size_t)(n0 + 1) * H_DIM + hh] = hi + bv + g_ce[(size_t)(n0 + 1) * H_DIM + hh];
            }
        }
    }
}

// ---------------- Kernel Z: zero class sums ----------------
__global__ void kZ() {
    int i = blockIdx.x * 256 + threadIdx.x;
    if (i < C_CLS * H_DIM) g_classsum[i] = 0.f;
}

// ---------------- Kernel B: per-class reduction ----------------
__global__ void __launch_bounds__(256) kB(const int* __restrict__ labels) {
    __shared__ float part[C_CLS * H_DIM];
    const int t = threadIdx.x;
    #pragma unroll
    for (int c = 0; c < C_CLS; c++) part[c * H_DIM + t] = 0.f;
    __syncthreads();
    const int base = blockIdx.x * 125;   // 112 blocks * 125 = 14000
    for (int j = 0; j < 125; j++) {
        int node = base + j;
        int c = labels[node];
        part[c * H_DIM + t] += g_rawret[(size_t)node * H_DIM + t];
    }
    __syncthreads();
    #pragma unroll
    for (int c = 0; c < C_CLS; c++)
        atomicAdd(&g_classsum[c * H_DIM + t], part[c * H_DIM + t]);
}

// ---------------- Kernel Norm: 1/||classsum_c|| ----------------
__global__ void kNorm() {
    int w = threadIdx.x >> 5, lane = threadIdx.x & 31;
    if (w < C_CLS) {
        float sq = 0.f;
        #pragma unroll
        for (int i = 0; i < 8; i++) {
            float v = g_classsum[w * H_DIM + lane + 32 * i];
            sq += v * v;
        }
        #pragma unroll
        for (int o = 16; o; o >>= 1) sq += __shfl_xor_sync(0xffffffffu, sq, o);
        if (lane == 0) g_invn[w] = 1.f / fmaxf(sqrtf(sq), (float)PER_CLASS * EPSF);
    }
}

// ---------------- Kernel C: final cos + softmax over classes ----------------
__global__ void __launch_bounds__(256) kC(float* __restrict__ out) {
    __shared__ float cs[C_CLS * H_DIM];
    __shared__ float invn_s[8];
    const int t = threadIdx.x;
    #pragma unroll
    for (int c = 0; c < C_CLS; c++) cs[c * H_DIM + t] = g_classsum[c * H_DIM + t];
    if (t < C_CLS) invn_s[t] = g_invn[t];
    __syncthreads();
    const int lane = t & 31, wid = t >> 5;
    const int n = blockIdx.x * 8 + wid;
    if (n >= N_NODES) return;
    const float4* rr4 = reinterpret_cast<const float4*>(g_rawret + (size_t)n * H_DIM);
    float4 r0 = rr4[lane], r1 = rr4[32 + lane];
    float nrm = dot4(r0, r0) + dot4(r1, r1);
    float d[C_CLS];
    const float4* cs4 = reinterpret_cast<const float4*>(cs);
    #pragma unroll
    for (int c = 0; c < C_CLS; c++) {
        float4 a0 = cs4[c * 64 + lane], a1 = cs4[c * 64 + 32 + lane];
        d[c] = dot4(r0, a0) + dot4(r1, a1);
    }
    #pragma unroll
    for (int o = 16; o; o >>= 1) {
        nrm += __shfl_xor_sync(0xffffffffu, nrm, o);
        #pragma unroll
        for (int c = 0; c < C_CLS; c++) d[c] += __shfl_xor_sync(0xffffffffu, d[c], o);
    }
    float inv_r = 1.f / fmaxf(sqrtf(nrm), EPSF);
    float cosv[C_CLS];
    float mx = -INFINITY;
    #pragma unroll
    for (int c = 0; c < C_CLS; c++) {
        cosv[c] = d[c] * inv_r * invn_s[c];
        mx = fmaxf(mx, cosv[c]);
    }
    float ssum = 0.f;
    #pragma unroll
    for (int c = 0; c < C_CLS; c++) {
        cosv[c] = __expf(cosv[c] - mx);
        ssum += cosv[c];
    }
    float inv = 1.f / ssum;
    if (lane < C_CLS) out[n * C_CLS + lane] = cosv[lane] * inv;
}

extern "C" void kernel_launch(void* const* d_in, const int* in_sizes, int n_in,
                              void* d_out, int out_size) {
    const float* emb    = (const float*)d_in[0];
    const float* w_self = (const float*)d_in[1];
    const float* w_n    = (const float*)d_in[2];
    const float* w_n2   = (const float*)d_in[3];
    const float* W1     = (const float*)d_in[4];
    const float* b1     = (const float*)d_in[5];
    const float* W2     = (const float*)d_in[6];
    const float* b2     = (const float*)d_in[7];
    const int*   idx    = (const int*)d_in[8];
    const int*   nbr    = (const int*)d_in[9];
    const int*   nbr2   = (const int*)d_in[10];
    const int*   labels = (const int*)d_in[11];
    float* out = (float*)d_out;

    const int smemA  = (int)sizeof(SmemA);
    const int smemAd = (int)sizeof(SmemAd);
    cudaFuncSetAttribute(kA, cudaFuncAttributeMaxDynamicSharedMemorySize, smemA);
    cudaFuncSetAttribute(kAdapt, cudaFuncAttributeMaxDynamicSharedMemorySize, smemAd);

    kZ<<<C_CLS, 256>>>();
    kA<<<N_NODES, 256, smemA>>>(emb, w_self, w_n, w_n2, idx, nbr, nbr2);
    kAdapt<<<(N_NODES + AB_N - 1) / AB_N, 256, smemAd>>>(W1, b1, W2, b2);
    kB<<<112, 256>>>(labels);
    kNorm<<<1, 256>>>();
    kC<<<(N_NODES + 7) / 8, 256>>>(out);
}